// round 1
// baseline (speedup 1.0000x reference)
#include <cuda_runtime.h>

typedef unsigned long long u64;
typedef unsigned int u32;

#define BATCH 512
#define NN    128
#define FF    256
#define HH    256
#define ROWS  (BATCH * NN)   // 65536

// Scratch (device globals: allocation-free rule)
__device__ float g_C[(size_t)ROWS * 512];  // [row][0:256]=AX, [256:512]=AH   (128 MiB)
__device__ float g_Z[(size_t)ROWS * HH];   // sigmoid z                        (64 MiB)
__device__ float g_R[(size_t)ROWS * HH];   // sigmoid r                        (64 MiB)

// ---------------- packed f32x2 helpers (FFMA2 path, B300) ----------------
__device__ __forceinline__ u64 pack2(float lo, float hi) {
    u64 r;
    asm("mov.b64 %0, {%1,%2};" : "=l"(r)
        : "r"(__float_as_uint(lo)), "r"(__float_as_uint(hi)));
    return r;
}
__device__ __forceinline__ float2 unpack2(u64 v) {
    u32 lo, hi;
    asm("mov.b64 {%0,%1}, %2;" : "=r"(lo), "=r"(hi) : "l"(v));
    return make_float2(__uint_as_float(lo), __uint_as_float(hi));
}
__device__ __forceinline__ u64 ffma2(u64 a, u64 b, u64 c) {
    u64 d;
    asm("fma.rn.f32x2 %0, %1, %2, %3;" : "=l"(d) : "l"(a), "l"(b), "l"(c));
    return d;
}

__device__ __forceinline__ float sigmoidf_fast(float x) {
    return 1.0f / (1.0f + __expf(-x));
}

// ============================================================================
// Kernel 1: per-batch C[b] = A[b] @ [X[b] | hidden[b]]
//   A[b]: [128,128] row-major; X/hidden[b]: [128,256] row-major.
//   grid (4, 512): blockIdx.x selects 128-col slice of the 512-wide output.
//   BM=128 (whole batch), BN=128, BK=8, 256 threads, 8x8 per thread, f32x2.
// ============================================================================
__global__ __launch_bounds__(256) void k1_prop(const float* __restrict__ A,
                                               const float* __restrict__ X,
                                               const float* __restrict__ Hid) {
    __shared__ float As[8][132];   // transposed A tile, padded vs bank conflict
    __shared__ float Bs[8][128];

    const int b    = blockIdx.y;
    const int nblk = blockIdx.x;   // 0,1 -> X cols ; 2,3 -> hidden cols
    const float* Ap = A + (size_t)b * NN * NN;
    const float* Bp = (nblk < 2 ? X : Hid) + (size_t)b * NN * FF + (size_t)(nblk & 1) * 128;

    const int t  = threadIdx.x;
    const int i8 = (t >> 4) * 8;       // m offset
    const int j8 = (t & 15) * 8;       // n offset
    const int ar = t >> 1, ac = (t & 1) * 4;     // A-tile load coords
    const int bk = t >> 5, bn = (t & 31) * 4;    // B-tile load coords

    u64 acc[8][4];
#pragma unroll
    for (int m = 0; m < 8; m++)
#pragma unroll
        for (int n = 0; n < 4; n++) acc[m][n] = 0ull;

    for (int kt = 0; kt < 128; kt += 8) {
        float4 av = *(const float4*)(Ap + (size_t)ar * 128 + kt + ac);
        As[ac + 0][ar] = av.x; As[ac + 1][ar] = av.y;
        As[ac + 2][ar] = av.z; As[ac + 3][ar] = av.w;
        *(float4*)&Bs[bk][bn] = *(const float4*)(Bp + (size_t)(kt + bk) * FF + bn);
        __syncthreads();
#pragma unroll
        for (int kk = 0; kk < 8; kk++) {
            float4 a0 = *(const float4*)&As[kk][i8];
            float4 a1 = *(const float4*)&As[kk][i8 + 4];
            float4 b0 = *(const float4*)&Bs[kk][j8];
            float4 b1 = *(const float4*)&Bs[kk][j8 + 4];
            u64 bp0 = pack2(b0.x, b0.y), bp1 = pack2(b0.z, b0.w);
            u64 bp2 = pack2(b1.x, b1.y), bp3 = pack2(b1.z, b1.w);
            float am[8] = {a0.x, a0.y, a0.z, a0.w, a1.x, a1.y, a1.z, a1.w};
#pragma unroll
            for (int m = 0; m < 8; m++) {
                u64 ap = pack2(am[m], am[m]);
                acc[m][0] = ffma2(ap, bp0, acc[m][0]);
                acc[m][1] = ffma2(ap, bp1, acc[m][1]);
                acc[m][2] = ffma2(ap, bp2, acc[m][2]);
                acc[m][3] = ffma2(ap, bp3, acc[m][3]);
            }
        }
        __syncthreads();
    }

    const size_t rowbase = (size_t)b * NN;
    const int colbase = nblk * 128 + j8;
#pragma unroll
    for (int m = 0; m < 8; m++) {
        size_t row = rowbase + i8 + m;
        float2 p0 = unpack2(acc[m][0]), p1 = unpack2(acc[m][1]);
        float2 p2 = unpack2(acc[m][2]), p3 = unpack2(acc[m][3]);
        *(float4*)&g_C[row * 512 + colbase]     = make_float4(p0.x, p0.y, p1.x, p1.y);
        *(float4*)&g_C[row * 512 + colbase + 4] = make_float4(p2.x, p2.y, p3.x, p3.y);
    }
}

// ============================================================================
// Kernel 2: z / r gates.  out = sigmoid(C @ [W1;W2] + bias)
//   M=65536 (rows of g_C), K=512 (stacked), N=256.
//   grid (2, 512, 2): x=col tile, y=batch(row tile of 128), z=gate (0=z,1=r).
// ============================================================================
__global__ __launch_bounds__(256) void k2_gate(const float* __restrict__ Wz1,
                                               const float* __restrict__ Wz2,
                                               const float* __restrict__ Wr1,
                                               const float* __restrict__ Wr2,
                                               const float* __restrict__ bz,
                                               const float* __restrict__ br) {
    __shared__ float As[8][132];
    __shared__ float Bs[8][128];

    const int gate = blockIdx.z;
    const float* W1   = gate ? Wr1 : Wz1;
    const float* W2   = gate ? Wr2 : Wz2;
    const float* bias = gate ? br  : bz;
    float* out        = gate ? g_R : g_Z;

    const int rb   = blockIdx.y;          // batch == 128-row tile
    const int col0 = blockIdx.x * 128;
    const float* Ap = g_C + (size_t)rb * 128 * 512;

    const int t  = threadIdx.x;
    const int i8 = (t >> 4) * 8;
    const int j8 = (t & 15) * 8;
    const int ar = t >> 1, ac = (t & 1) * 4;
    const int bk = t >> 5, bn = (t & 31) * 4;

    u64 acc[8][4];
#pragma unroll
    for (int m = 0; m < 8; m++)
#pragma unroll
        for (int n = 0; n < 4; n++) acc[m][n] = 0ull;

    for (int kt = 0; kt < 512; kt += 8) {
        float4 av = *(const float4*)(Ap + (size_t)ar * 512 + kt + ac);
        As[ac + 0][ar] = av.x; As[ac + 1][ar] = av.y;
        As[ac + 2][ar] = av.z; As[ac + 3][ar] = av.w;
        const float* Wp = (kt < 256) ? (W1 + (size_t)kt * HH)
                                     : (W2 + (size_t)(kt - 256) * HH);
        *(float4*)&Bs[bk][bn] = *(const float4*)(Wp + (size_t)bk * HH + col0 + bn);
        __syncthreads();
#pragma unroll
        for (int kk = 0; kk < 8; kk++) {
            float4 a0 = *(const float4*)&As[kk][i8];
            float4 a1 = *(const float4*)&As[kk][i8 + 4];
            float4 b0 = *(const float4*)&Bs[kk][j8];
            float4 b1 = *(const float4*)&Bs[kk][j8 + 4];
            u64 bp0 = pack2(b0.x, b0.y), bp1 = pack2(b0.z, b0.w);
            u64 bp2 = pack2(b1.x, b1.y), bp3 = pack2(b1.z, b1.w);
            float am[8] = {a0.x, a0.y, a0.z, a0.w, a1.x, a1.y, a1.z, a1.w};
#pragma unroll
            for (int m = 0; m < 8; m++) {
                u64 ap = pack2(am[m], am[m]);
                acc[m][0] = ffma2(ap, bp0, acc[m][0]);
                acc[m][1] = ffma2(ap, bp1, acc[m][1]);
                acc[m][2] = ffma2(ap, bp2, acc[m][2]);
                acc[m][3] = ffma2(ap, bp3, acc[m][3]);
            }
        }
        __syncthreads();
    }

#pragma unroll
    for (int m = 0; m < 8; m++) {
        const int lr = i8 + m;                     // local row == n index (bias row)
        const size_t row = (size_t)rb * 128 + lr;
        float4 bb0 = *(const float4*)(bias + (size_t)lr * HH + col0 + j8);
        float4 bb1 = *(const float4*)(bias + (size_t)lr * HH + col0 + j8 + 4);
        float2 p0 = unpack2(acc[m][0]), p1 = unpack2(acc[m][1]);
        float2 p2 = unpack2(acc[m][2]), p3 = unpack2(acc[m][3]);
        float4 o0, o1;
        o0.x = sigmoidf_fast(p0.x + bb0.x);
        o0.y = sigmoidf_fast(p0.y + bb0.y);
        o0.z = sigmoidf_fast(p1.x + bb0.z);
        o0.w = sigmoidf_fast(p1.y + bb0.w);
        o1.x = sigmoidf_fast(p2.x + bb1.x);
        o1.y = sigmoidf_fast(p2.y + bb1.y);
        o1.z = sigmoidf_fast(p3.x + bb1.z);
        o1.w = sigmoidf_fast(p3.y + bb1.w);
        *(float4*)&out[row * HH + col0 + j8]     = o0;
        *(float4*)&out[row * HH + col0 + j8 + 4] = o1;
    }
}

// ============================================================================
// Kernel 3: dual GEMM + fused GRU epilogue.
//   P1 = AX @ Wh1, P2 = AH @ Wh2 (both K=256), then
//   h = z*hidden + (1-z)*tanh(P1 + r*P2 + bias_h)
//   BM=128, BN=64, BK=8, 256 threads, 8x4 per thread, two accumulator sets.
//   grid (4, 512): x = 64-col tile, y = batch.
// ============================================================================
__global__ __launch_bounds__(256) void k3_h(const float* __restrict__ Wh1,
                                            const float* __restrict__ Wh2,
                                            const float* __restrict__ bh,
                                            const float* __restrict__ Hid,
                                            float* __restrict__ Out) {
    __shared__ float As1[8][132];
    __shared__ float As2[8][132];
    __shared__ float Bs1[8][64];
    __shared__ float Bs2[8][64];

    const int rb   = blockIdx.y;
    const int col0 = blockIdx.x * 64;
    const float* Ap = g_C + (size_t)rb * 128 * 512;

    const int t  = threadIdx.x;
    const int i8 = (t >> 4) * 8;
    const int j4 = (t & 15) * 4;
    const int ar = t >> 1, ac = (t & 1) * 4;
    const int bk = t >> 5, bn = (t & 31) * 2;

    u64 acc1[8][2], acc2[8][2];
#pragma unroll
    for (int m = 0; m < 8; m++) {
        acc1[m][0] = acc1[m][1] = 0ull;
        acc2[m][0] = acc2[m][1] = 0ull;
    }

    for (int kt = 0; kt < 256; kt += 8) {
        float4 a1 = *(const float4*)(Ap + (size_t)ar * 512 + kt + ac);
        float4 a2 = *(const float4*)(Ap + (size_t)ar * 512 + 256 + kt + ac);
        As1[ac + 0][ar] = a1.x; As1[ac + 1][ar] = a1.y;
        As1[ac + 2][ar] = a1.z; As1[ac + 3][ar] = a1.w;
        As2[ac + 0][ar] = a2.x; As2[ac + 1][ar] = a2.y;
        As2[ac + 2][ar] = a2.z; As2[ac + 3][ar] = a2.w;
        *(float2*)&Bs1[bk][bn] = *(const float2*)(Wh1 + (size_t)(kt + bk) * HH + col0 + bn);
        *(float2*)&Bs2[bk][bn] = *(const float2*)(Wh2 + (size_t)(kt + bk) * HH + col0 + bn);
        __syncthreads();
#pragma unroll
        for (int kk = 0; kk < 8; kk++) {
            float4 a1v0 = *(const float4*)&As1[kk][i8];
            float4 a1v1 = *(const float4*)&As1[kk][i8 + 4];
            float4 a2v0 = *(const float4*)&As2[kk][i8];
            float4 a2v1 = *(const float4*)&As2[kk][i8 + 4];
            float4 b1v = *(const float4*)&Bs1[kk][j4];
            float4 b2v = *(const float4*)&Bs2[kk][j4];
            u64 bp1a = pack2(b1v.x, b1v.y), bp1b = pack2(b1v.z, b1v.w);
            u64 bp2a = pack2(b2v.x, b2v.y), bp2b = pack2(b2v.z, b2v.w);
            float a1m[8] = {a1v0.x, a1v0.y, a1v0.z, a1v0.w, a1v1.x, a1v1.y, a1v1.z, a1v1.w};
            float a2m[8] = {a2v0.x, a2v0.y, a2v0.z, a2v0.w, a2v1.x, a2v1.y, a2v1.z, a2v1.w};
#pragma unroll
            for (int m = 0; m < 8; m++) {
                u64 ap1 = pack2(a1m[m], a1m[m]);
                u64 ap2 = pack2(a2m[m], a2m[m]);
                acc1[m][0] = ffma2(ap1, bp1a, acc1[m][0]);
                acc1[m][1] = ffma2(ap1, bp1b, acc1[m][1]);
                acc2[m][0] = ffma2(ap2, bp2a, acc2[m][0]);
                acc2[m][1] = ffma2(ap2, bp2b, acc2[m][1]);
            }
        }
        __syncthreads();
    }

#pragma unroll
    for (int m = 0; m < 8; m++) {
        const int lr = i8 + m;
        const size_t row = (size_t)rb * 128 + lr;
        const size_t off = row * HH + col0 + j4;
        float4 zv = *(const float4*)&g_Z[off];
        float4 rv = *(const float4*)&g_R[off];
        float4 hv = *(const float4*)(Hid + off);
        float4 bv = *(const float4*)(bh + (size_t)lr * HH + col0 + j4);
        float2 p10 = unpack2(acc1[m][0]), p11 = unpack2(acc1[m][1]);
        float2 p20 = unpack2(acc2[m][0]), p21 = unpack2(acc2[m][1]);
        float4 o;
        o.x = zv.x * hv.x + (1.0f - zv.x) * tanhf(p10.x + rv.x * p20.x + bv.x);
        o.y = zv.y * hv.y + (1.0f - zv.y) * tanhf(p10.y + rv.y * p20.y + bv.y);
        o.z = zv.z * hv.z + (1.0f - zv.z) * tanhf(p11.x + rv.z * p21.x + bv.z);
        o.w = zv.w * hv.w + (1.0f - zv.w) * tanhf(p11.y + rv.w * p21.y + bv.w);
        *(float4*)&Out[off] = o;
    }
}

// ============================================================================
extern "C" void kernel_launch(void* const* d_in, const int* in_sizes, int n_in,
                              void* d_out, int out_size) {
    (void)in_sizes; (void)n_in; (void)out_size;
    const float* X      = (const float*)d_in[0];
    const float* A      = (const float*)d_in[1];
    const float* hidden = (const float*)d_in[2];
    const float* Wz1    = (const float*)d_in[3];
    const float* Wz2    = (const float*)d_in[4];
    const float* Wr1    = (const float*)d_in[5];
    const float* Wr2    = (const float*)d_in[6];
    const float* Wh1    = (const float*)d_in[7];
    const float* Wh2    = (const float*)d_in[8];
    const float* bz     = (const float*)d_in[9];
    const float* br     = (const float*)d_in[10];
    const float* bh     = (const float*)d_in[11];
    float* out          = (float*)d_out;

    k1_prop<<<dim3(4, 512), 256>>>(A, X, hidden);
    k2_gate<<<dim3(2, 512, 2), 256>>>(Wz1, Wz2, Wr1, Wr2, bz, br);
    k3_h<<<dim3(4, 512), 256>>>(Wh1, Wh2, bh, hidden, out);
}

// round 3
// speedup vs baseline: 1.4746x; 1.4746x over previous
#include <cuda_runtime.h>
#include <cuda_fp16.h>

typedef unsigned int u32;

#define B_    512
#define ROWS  65536   // B_*128

// ---------------------------------------------------------------------------
// Device-global scratch (allocation-free rule)
// ---------------------------------------------------------------------------
__device__ __half g_A_hi[(size_t)B_ * 128 * 128];
__device__ __half g_A_lo[(size_t)B_ * 128 * 128];
__device__ __half g_Xt[(size_t)B_ * 256 * 128];     // [b][feat][tok]
__device__ __half g_Ht[(size_t)B_ * 256 * 128];
__device__ __half g_C_hi[(size_t)ROWS * 512];       // [row][0:256]=AX,[256:512]=AH
__device__ __half g_C_lo[(size_t)ROWS * 512];
__device__ float  g_Z[(size_t)ROWS * 256];
__device__ float  g_R[(size_t)ROWS * 256];
__device__ __half g_Wz[256 * 512];                  // [n][k] k<256: Wz1^T, k>=256: Wz2^T
__device__ __half g_Wr[256 * 512];
__device__ __half g_Wh1[256 * 256];
__device__ __half g_Wh2[256 * 256];

// ---------------------------------------------------------------------------
// Helpers
// ---------------------------------------------------------------------------
__device__ __forceinline__ u32 smem_u32(const void* p) {
    u32 a;
    asm("{ .reg .u64 t; cvta.to.shared.u64 t, %1; cvt.u32.u64 %0, t; }" : "=r"(a) : "l"(p));
    return a;
}
__device__ __forceinline__ void ldsm4(u32* r, u32 addr) {
    asm volatile("ldmatrix.sync.aligned.m8n8.x4.shared.b16 {%0,%1,%2,%3}, [%4];"
                 : "=r"(r[0]), "=r"(r[1]), "=r"(r[2]), "=r"(r[3]) : "r"(addr));
}
__device__ __forceinline__ void mma16816(float* d, const u32* a, const u32* b) {
    asm volatile(
        "mma.sync.aligned.m16n8k16.row.col.f32.f16.f16.f32 "
        "{%0,%1,%2,%3}, {%4,%5,%6,%7}, {%8,%9}, {%0,%1,%2,%3};"
        : "+f"(d[0]), "+f"(d[1]), "+f"(d[2]), "+f"(d[3])
        : "r"(a[0]), "r"(a[1]), "r"(a[2]), "r"(a[3]), "r"(b[0]), "r"(b[1]));
}
__device__ __forceinline__ float sigmoidf_fast(float x) {
    return 1.0f / (1.0f + __expf(-x));
}
__device__ __forceinline__ void split2(float x, __half& h, __half& l) {
    h = __float2half_rn(x);
    l = __float2half_rn(x - __half2float(h));
}

// SMEM tile: rows x 64 halfs, padded to 72 halfs (144 B) per row -> conflict-free
// ldmatrix (36 words/row: 8 consecutive rows hit distinct 4-bank groups).
#define STRB 144
#define TILE_BYTES 18432          // 128 * 144
#define OFF_AHI 0
#define OFF_ALO 18432
#define OFF_B   36864
#define SMEM_TOTAL 55296

// Copy [rows x 64] halfs (global stride gs halfs) into padded SMEM tile.
__device__ __forceinline__ void ld_tile(char* s, const __half* g, int rows, int gs, int tid) {
    int total = rows * 8;
    for (int i = tid; i < total; i += 256) {
        int r = i >> 3, c = i & 7;
        *(uint4*)(s + r * STRB + c * 16) = *(const uint4*)(g + (size_t)r * gs + c * 8);
    }
}

// ---------------------------------------------------------------------------
// Conversion kernels
// ---------------------------------------------------------------------------
__global__ __launch_bounds__(256) void conv_A(const float* __restrict__ A) {
    size_t i = ((size_t)blockIdx.x * 256 + threadIdx.x) * 4;
    float4 v = *(const float4*)(A + i);
    __half h0, h1, h2, h3, l0, l1, l2, l3;
    split2(v.x, h0, l0); split2(v.y, h1, l1); split2(v.z, h2, l2); split2(v.w, h3, l3);
    __half2 hv0 = __halves2half2(h0, h1), hv1 = __halves2half2(h2, h3);
    __half2 lv0 = __halves2half2(l0, l1), lv1 = __halves2half2(l2, l3);
    *(uint2*)(g_A_hi + i) = make_uint2(*(u32*)&hv0, *(u32*)&hv1);
    *(uint2*)(g_A_lo + i) = make_uint2(*(u32*)&lv0, *(u32*)&lv1);
}

// Transpose X/hidden per batch: [tok 128][feat 256] -> [feat 256][tok 128], fp16
__global__ __launch_bounds__(256) void conv_XH(const float* __restrict__ X,
                                               const float* __restrict__ Hd) {
    int z = blockIdx.z;
    int b = z & (B_ - 1);
    const float* src = (z < B_) ? X : Hd;
    __half* dst = (z < B_) ? g_Xt : g_Ht;
    __shared__ float s[32][33];
    int tx = threadIdx.x & 31, ty = threadIdx.x >> 5;
    int f0 = blockIdx.x * 32, t0 = blockIdx.y * 32;
    const float* sp = src + (size_t)b * 128 * 256;
#pragma unroll
    for (int r = 0; r < 4; r++)
        s[ty + 8 * r][tx] = sp[(size_t)(t0 + ty + 8 * r) * 256 + f0 + tx];
    __syncthreads();
    size_t dbase = (size_t)b * 256 * 128;
#pragma unroll
    for (int r = 0; r < 4; r++)
        dst[dbase + (size_t)(f0 + ty + 8 * r) * 128 + t0 + tx] =
            __float2half_rn(s[tx][ty + 8 * r]);
}

// Transpose weights: dst[n][koff+k] = W[k][n], fp16
__global__ __launch_bounds__(256) void conv_W(const float* __restrict__ Wz1, const float* __restrict__ Wz2,
                                              const float* __restrict__ Wr1, const float* __restrict__ Wr2,
                                              const float* __restrict__ Wh1, const float* __restrict__ Wh2) {
    int job = blockIdx.z;
    const float* src; __half* dst; int koff, stride;
    switch (job) {
        case 0:  src = Wz1; dst = g_Wz;  koff = 0;   stride = 512; break;
        case 1:  src = Wz2; dst = g_Wz;  koff = 256; stride = 512; break;
        case 2:  src = Wr1; dst = g_Wr;  koff = 0;   stride = 512; break;
        case 3:  src = Wr2; dst = g_Wr;  koff = 256; stride = 512; break;
        case 4:  src = Wh1; dst = g_Wh1; koff = 0;   stride = 256; break;
        default: src = Wh2; dst = g_Wh2; koff = 0;   stride = 256; break;
    }
    __shared__ float s[32][33];
    int tx = threadIdx.x & 31, ty = threadIdx.x >> 5;
    int n0 = blockIdx.x * 32, k0 = blockIdx.y * 32;
#pragma unroll
    for (int r = 0; r < 4; r++)
        s[ty + 8 * r][tx] = src[(size_t)(k0 + ty + 8 * r) * 256 + n0 + tx];
    __syncthreads();
#pragma unroll
    for (int r = 0; r < 4; r++)
        dst[(size_t)(n0 + ty + 8 * r) * stride + koff + k0 + tx] =
            __float2half_rn(s[tx][ty + 8 * r]);
}

// ---------------------------------------------------------------------------
// Shared MMA chunk: 128(M) x 128(N) x 64(K), split-A 2-term.
// Warp grid 2(M) x 4(N), warp tile 64x32. acc[4][4][4].
// ---------------------------------------------------------------------------
__device__ __forceinline__ void mma_chunk_128x128(float acc[4][4][4], u32 sb,
                                                  u32 aoff, u32 boff) {
#pragma unroll
    for (int k16 = 0; k16 < 4; k16++) {
        u32 bf[2][4];
        ldsm4(bf[0], sb + OFF_B + boff + k16 * 32);
        ldsm4(bf[1], sb + OFF_B + boff + 16 * STRB + k16 * 32);
#pragma unroll
        for (int mi = 0; mi < 4; mi++) {
            u32 ah[4], al[4];
            ldsm4(ah, sb + OFF_AHI + aoff + mi * 16 * STRB + k16 * 32);
            ldsm4(al, sb + OFF_ALO + aoff + mi * 16 * STRB + k16 * 32);
#pragma unroll
            for (int ni = 0; ni < 4; ni++) {
                const u32* bp = &bf[ni >> 1][(ni & 1) * 2];
                mma16816(acc[mi][ni], ah, bp);
                mma16816(acc[mi][ni], al, bp);
            }
        }
    }
}

// ---------------------------------------------------------------------------
// k1: D[128 tok, 128 feat] = A_b @ (X|H)_b slice, -> C hi/lo fp16
// grid (4, 512): x = hsel*2 + nb, y = batch
// ---------------------------------------------------------------------------
__global__ __launch_bounds__(256, 2) void k1() {
    extern __shared__ char sm[];
    const int tid = threadIdx.x, lane = tid & 31, wid = tid >> 5;
    const int wm = wid >> 2, wn = wid & 3;
    const int hsel = blockIdx.x >> 1, nb = blockIdx.x & 1, b = blockIdx.y;

    const __half* Ah = g_A_hi + (size_t)b * 16384;
    const __half* Al = g_A_lo + (size_t)b * 16384;
    const __half* Bp = (hsel ? g_Ht : g_Xt) + (size_t)b * 32768 + (size_t)nb * 128 * 128;

    u32 sb = smem_u32(sm);
    u32 aoff = (u32)((wm * 64 + (lane & 15)) * STRB + (lane >> 4) * 16);
    u32 boff = (u32)((wn * 32 + (lane & 7) + ((lane >> 4) << 3)) * STRB + ((lane >> 3) & 1) * 16);

    float acc[4][4][4];
#pragma unroll
    for (int a = 0; a < 4; a++)
#pragma unroll
        for (int c = 0; c < 4; c++)
#pragma unroll
            for (int d = 0; d < 4; d++) acc[a][c][d] = 0.0f;

    for (int ch = 0; ch < 2; ch++) {
        __syncthreads();
        ld_tile(sm + OFF_AHI, Ah + ch * 64, 128, 128, tid);
        ld_tile(sm + OFF_ALO, Al + ch * 64, 128, 128, tid);
        ld_tile(sm + OFF_B,   Bp + ch * 64, 128, 128, tid);
        __syncthreads();
        mma_chunk_128x128(acc, sb, aoff, boff);
    }

    const size_t rowbase = (size_t)b * 128;
    const int colb = hsel * 256 + nb * 128 + wn * 32;
#pragma unroll
    for (int mi = 0; mi < 4; mi++) {
#pragma unroll
        for (int ni = 0; ni < 4; ni++) {
            int r0 = wm * 64 + mi * 16 + (lane >> 2);
            int c  = colb + ni * 8 + (lane & 3) * 2;
#pragma unroll
            for (int half_ = 0; half_ < 2; half_++) {
                size_t row = rowbase + r0 + half_ * 8;
                float x0 = acc[mi][ni][half_ * 2], x1 = acc[mi][ni][half_ * 2 + 1];
                __half h0, l0, h1, l1;
                split2(x0, h0, l0); split2(x1, h1, l1);
                *(__half2*)(g_C_hi + row * 512 + c) = __halves2half2(h0, h1);
                *(__half2*)(g_C_lo + row * 512 + c) = __halves2half2(l0, l1);
            }
        }
    }
}

// ---------------------------------------------------------------------------
// k2: Z/R = sigmoid(C @ W^T + bias), K=512. grid (4, 512): x = gate*2+nb, y = rowtile
// ---------------------------------------------------------------------------
__global__ __launch_bounds__(256, 2) void k2(const float* __restrict__ bias_z,
                                             const float* __restrict__ bias_r) {
    extern __shared__ char sm[];
    const int tid = threadIdx.x, lane = tid & 31, wid = tid >> 5;
    const int wm = wid >> 2, wn = wid & 3;
    const int gate = blockIdx.x >> 1, nb = blockIdx.x & 1, rt = blockIdx.y;

    const __half* Ah = g_C_hi + (size_t)rt * 128 * 512;
    const __half* Al = g_C_lo + (size_t)rt * 128 * 512;
    const __half* Bp = (gate ? g_Wr : g_Wz) + (size_t)nb * 128 * 512;

    u32 sb = smem_u32(sm);
    u32 aoff = (u32)((wm * 64 + (lane & 15)) * STRB + (lane >> 4) * 16);
    u32 boff = (u32)((wn * 32 + (lane & 7) + ((lane >> 4) << 3)) * STRB + ((lane >> 3) & 1) * 16);

    float acc[4][4][4];
#pragma unroll
    for (int a = 0; a < 4; a++)
#pragma unroll
        for (int c = 0; c < 4; c++)
#pragma unroll
            for (int d = 0; d < 4; d++) acc[a][c][d] = 0.0f;

    for (int ch = 0; ch < 8; ch++) {
        __syncthreads();
        ld_tile(sm + OFF_AHI, Ah + ch * 64, 128, 512, tid);
        ld_tile(sm + OFF_ALO, Al + ch * 64, 128, 512, tid);
        ld_tile(sm + OFF_B,   Bp + ch * 64, 128, 512, tid);
        __syncthreads();
        mma_chunk_128x128(acc, sb, aoff, boff);
    }

    float* out = gate ? g_R : g_Z;
    const float* bias = gate ? bias_r : bias_z;
#pragma unroll
    for (int mi = 0; mi < 4; mi++) {
#pragma unroll
        for (int ni = 0; ni < 4; ni++) {
            int lr0 = wm * 64 + mi * 16 + (lane >> 2);
            int c   = nb * 128 + wn * 32 + ni * 8 + (lane & 3) * 2;
#pragma unroll
            for (int half_ = 0; half_ < 2; half_++) {
                int lr = lr0 + half_ * 8;
                float2 bb = *(const float2*)(bias + (size_t)lr * 256 + c);
                float2 o;
                o.x = sigmoidf_fast(acc[mi][ni][half_ * 2]     + bb.x);
                o.y = sigmoidf_fast(acc[mi][ni][half_ * 2 + 1] + bb.y);
                *(float2*)(out + ((size_t)rt * 128 + lr) * 256 + c) = o;
            }
        }
    }
}

// ---------------------------------------------------------------------------
// k3: P1 = AX@Wh1, P2 = AH@Wh2 (K=256 each), fused GRU epilogue.
// Block 128x64; warp tile 64x16. grid (4, 512): x = colblk, y = rowtile
// ---------------------------------------------------------------------------
__global__ __launch_bounds__(256, 2) void k3(const float* __restrict__ bias_h,
                                             const float* __restrict__ hidden,
                                             float* __restrict__ Out) {
    extern __shared__ char sm[];
    const int tid = threadIdx.x, lane = tid & 31, wid = tid >> 5;
    const int wm = wid >> 2, wn = wid & 3;
    const int cb = blockIdx.x, rt = blockIdx.y;

    const __half* Ah = g_C_hi + (size_t)rt * 128 * 512;
    const __half* Al = g_C_lo + (size_t)rt * 128 * 512;

    u32 sb = smem_u32(sm);
    u32 aoff = (u32)((wm * 64 + (lane & 15)) * STRB + (lane >> 4) * 16);
    u32 boff = (u32)((wn * 16 + (lane & 7) + ((lane >> 4) << 3)) * STRB + ((lane >> 3) & 1) * 16);

    float acc[2][4][2][4];   // [P][mi][ni][4]
#pragma unroll
    for (int p = 0; p < 2; p++)
#pragma unroll
        for (int a = 0; a < 4; a++)
#pragma unroll
            for (int c = 0; c < 2; c++)
#pragma unroll
                for (int d = 0; d < 4; d++) acc[p][a][c][d] = 0.0f;

#pragma unroll
    for (int P = 0; P < 2; P++) {
        const __half* Bbase = (P ? g_Wh2 : g_Wh1) + (size_t)cb * 64 * 256;
        for (int ch = 0; ch < 4; ch++) {
            __syncthreads();
            ld_tile(sm + OFF_AHI, Ah + P * 256 + ch * 64, 128, 512, tid);
            ld_tile(sm + OFF_ALO, Al + P * 256 + ch * 64, 128, 512, tid);
            ld_tile(sm + OFF_B,   Bbase + ch * 64, 64, 256, tid);
            __syncthreads();
#pragma unroll
            for (int k16 = 0; k16 < 4; k16++) {
                u32 bf[4];
                ldsm4(bf, sb + OFF_B + boff + k16 * 32);
#pragma unroll
                for (int mi = 0; mi < 4; mi++) {
                    u32 ah[4], al[4];
                    ldsm4(ah, sb + OFF_AHI + aoff + mi * 16 * STRB + k16 * 32);
                    ldsm4(al, sb + OFF_ALO + aoff + mi * 16 * STRB + k16 * 32);
#pragma unroll
                    for (int ni = 0; ni < 2; ni++) {
                        mma16816(acc[P][mi][ni], ah, &bf[ni * 2]);
                        mma16816(acc[P][mi][ni], al, &bf[ni * 2]);
                    }
                }
            }
        }
    }

#pragma unroll
    for (int mi = 0; mi < 4; mi++) {
#pragma unroll
        for (int ni = 0; ni < 2; ni++) {
            int lr0 = wm * 64 + mi * 16 + (lane >> 2);
            int c   = cb * 64 + wn * 16 + ni * 8 + (lane & 3) * 2;
#pragma unroll
            for (int half_ = 0; half_ < 2; half_++) {
                int lr = lr0 + half_ * 8;
                size_t off = ((size_t)rt * 128 + lr) * 256 + c;
                float2 zv = *(const float2*)(g_Z + off);
                float2 rv = *(const float2*)(g_R + off);
                float2 hv = *(const float2*)(hidden + off);
                float2 bv = *(const float2*)(bias_h + (size_t)lr * 256 + c);
                float p1x = acc[0][mi][ni][half_ * 2],     p2x = acc[1][mi][ni][half_ * 2];
                float p1y = acc[0][mi][ni][half_ * 2 + 1], p2y = acc[1][mi][ni][half_ * 2 + 1];
                float2 o;
                o.x = zv.x * hv.x + (1.0f - zv.x) * tanhf(p1x + rv.x * p2x + bv.x);
                o.y = zv.y * hv.y + (1.0f - zv.y) * tanhf(p1y + rv.y * p2y + bv.y);
                *(float2*)(Out + off) = o;
            }
        }
    }
}

// ---------------------------------------------------------------------------
extern "C" void kernel_launch(void* const* d_in, const int* in_sizes, int n_in,
                              void* d_out, int out_size) {
    (void)in_sizes; (void)n_in; (void)out_size;
    const float* X      = (const float*)d_in[0];
    const float* A      = (const float*)d_in[1];
    const float* hidden = (const float*)d_in[2];
    const float* Wz1    = (const float*)d_in[3];
    const float* Wz2    = (const float*)d_in[4];
    const float* Wr1    = (const float*)d_in[5];
    const float* Wr2    = (const float*)d_in[6];
    const float* Wh1    = (const float*)d_in[7];
    const float* Wh2    = (const float*)d_in[8];
    const float* bz     = (const float*)d_in[9];
    const float* br     = (const float*)d_in[10];
    const float* bh     = (const float*)d_in[11];
    float* out          = (float*)d_out;

    static bool attr_done = false;
    if (!attr_done) {
        cudaFuncSetAttribute(k1, cudaFuncAttributeMaxDynamicSharedMemorySize, SMEM_TOTAL);
        cudaFuncSetAttribute(k2, cudaFuncAttributeMaxDynamicSharedMemorySize, SMEM_TOTAL);
        cudaFuncSetAttribute(k3, cudaFuncAttributeMaxDynamicSharedMemorySize, SMEM_TOTAL);
        attr_done = true;
    }

    conv_A<<<8192, 256>>>(A);
    conv_XH<<<dim3(8, 4, 1024), 256>>>(X, hidden);
    conv_W<<<dim3(8, 8, 6), 256>>>(Wz1, Wz2, Wr1, Wr2, Wh1, Wh2);

    k1<<<dim3(4, 512), 256, SMEM_TOTAL>>>();
    k2<<<dim3(4, 512), 256, SMEM_TOTAL>>>(bz, br);
    k3<<<dim3(4, 512), 256, SMEM_TOTAL>>>(bh, hidden, out);
}

// round 4
// speedup vs baseline: 2.7498x; 1.8648x over previous
#include <cuda_runtime.h>
#include <cuda_fp16.h>

typedef unsigned int u32;

#define B_    512
#define ROWS  65536   // B_*128

// ---------------------------------------------------------------------------
// Device-global scratch (allocation-free rule)
// ---------------------------------------------------------------------------
__device__ __half g_A_hi[(size_t)B_ * 128 * 128];
__device__ __half g_A_lo[(size_t)B_ * 128 * 128];
__device__ __half g_Xt[(size_t)B_ * 256 * 128];     // [b][feat][tok]
__device__ __half g_Ht[(size_t)B_ * 256 * 128];
__device__ __half g_C_hi[(size_t)ROWS * 512];       // [row][0:256]=AX,[256:512]=AH
__device__ __half g_C_lo[(size_t)ROWS * 512];
__device__ float  g_Z[(size_t)ROWS * 256];
__device__ float  g_R[(size_t)ROWS * 256];
__device__ __half g_Wz[256 * 512];                  // [n][k] k<256: Wz1^T, k>=256: Wz2^T
__device__ __half g_Wr[256 * 512];
__device__ __half g_Wh1[256 * 256];
__device__ __half g_Wh2[256 * 256];

// ---------------------------------------------------------------------------
// Helpers
// ---------------------------------------------------------------------------
__device__ __forceinline__ u32 smem_u32(const void* p) {
    u32 a;
    asm("{ .reg .u64 t; cvta.to.shared.u64 t, %1; cvt.u32.u64 %0, t; }" : "=r"(a) : "l"(p));
    return a;
}
__device__ __forceinline__ void ldsm4(u32* r, u32 addr) {
    asm volatile("ldmatrix.sync.aligned.m8n8.x4.shared.b16 {%0,%1,%2,%3}, [%4];"
                 : "=r"(r[0]), "=r"(r[1]), "=r"(r[2]), "=r"(r[3]) : "r"(addr));
}
__device__ __forceinline__ void mma16816(float* d, const u32* a, const u32* b) {
    asm volatile(
        "mma.sync.aligned.m16n8k16.row.col.f32.f16.f16.f32 "
        "{%0,%1,%2,%3}, {%4,%5,%6,%7}, {%8,%9}, {%0,%1,%2,%3};"
        : "+f"(d[0]), "+f"(d[1]), "+f"(d[2]), "+f"(d[3])
        : "r"(a[0]), "r"(a[1]), "r"(a[2]), "r"(a[3]), "r"(b[0]), "r"(b[1]));
}
__device__ __forceinline__ float sigmoidf_fast(float x) {
    return 1.0f / (1.0f + __expf(-x));
}
__device__ __forceinline__ void split2(float x, __half& h, __half& l) {
    h = __float2half_rn(x);
    l = __float2half_rn(x - __half2float(h));
}
__device__ __forceinline__ void cp16(u32 sdst, const void* gsrc) {
    asm volatile(
        "{ .reg .u64 p; cvta.to.global.u64 p, %1; cp.async.cg.shared.global [%0], [p], 16; }"
        :: "r"(sdst), "l"(gsrc) : "memory");
}
__device__ __forceinline__ void cp_commit() {
    asm volatile("cp.async.commit_group;" ::: "memory");
}
template <int N>
__device__ __forceinline__ void cp_wait() {
    asm volatile("cp.async.wait_group %0;" :: "n"(N) : "memory");
}

// SMEM tile: rows x 64 halfs, padded to 72 halfs (144 B) per row -> conflict-free
#define STRB 144
#define TILE_BYTES 18432          // 128 * 144
#define OFF_AHI 0
#define OFF_ALO 18432
#define OFF_B   36864
#define BUF_SZ  55296
#define SMEM_TOTAL 110592         // double buffered

// Async-copy a [rows x 64] half tile (global stride gs halfs) into padded SMEM.
__device__ __forceinline__ void cp_tile(u32 sdst, const __half* g, int rows, int gs, int tid) {
    int total = rows * 8;
    for (int i = tid; i < total; i += 256) {
        int r = i >> 3, c = i & 7;
        cp16(sdst + r * STRB + c * 16, g + (size_t)r * gs + c * 8);
    }
}

// ---------------------------------------------------------------------------
// Conversion kernels
// ---------------------------------------------------------------------------
__global__ __launch_bounds__(256) void conv_A(const float* __restrict__ A) {
    size_t i = ((size_t)blockIdx.x * 256 + threadIdx.x) * 4;
    float4 v = *(const float4*)(A + i);
    __half h0, h1, h2, h3, l0, l1, l2, l3;
    split2(v.x, h0, l0); split2(v.y, h1, l1); split2(v.z, h2, l2); split2(v.w, h3, l3);
    __half2 hv0 = __halves2half2(h0, h1), hv1 = __halves2half2(h2, h3);
    __half2 lv0 = __halves2half2(l0, l1), lv1 = __halves2half2(l2, l3);
    *(uint2*)(g_A_hi + i) = make_uint2(*(u32*)&hv0, *(u32*)&hv1);
    *(uint2*)(g_A_lo + i) = make_uint2(*(u32*)&lv0, *(u32*)&lv1);
}

__global__ __launch_bounds__(256) void conv_XH(const float* __restrict__ X,
                                               const float* __restrict__ Hd) {
    int z = blockIdx.z;
    int b = z & (B_ - 1);
    const float* src = (z < B_) ? X : Hd;
    __half* dst = (z < B_) ? g_Xt : g_Ht;
    __shared__ float s[32][33];
    int tx = threadIdx.x & 31, ty = threadIdx.x >> 5;
    int f0 = blockIdx.x * 32, t0 = blockIdx.y * 32;
    const float* sp = src + (size_t)b * 128 * 256;
#pragma unroll
    for (int r = 0; r < 4; r++)
        s[ty + 8 * r][tx] = sp[(size_t)(t0 + ty + 8 * r) * 256 + f0 + tx];
    __syncthreads();
    size_t dbase = (size_t)b * 256 * 128;
#pragma unroll
    for (int r = 0; r < 4; r++)
        dst[dbase + (size_t)(f0 + ty + 8 * r) * 128 + t0 + tx] =
            __float2half_rn(s[tx][ty + 8 * r]);
}

__global__ __launch_bounds__(256) void conv_W(const float* __restrict__ Wz1, const float* __restrict__ Wz2,
                                              const float* __restrict__ Wr1, const float* __restrict__ Wr2,
                                              const float* __restrict__ Wh1, const float* __restrict__ Wh2) {
    int job = blockIdx.z;
    const float* src; __half* dst; int koff, stride;
    switch (job) {
        case 0:  src = Wz1; dst = g_Wz;  koff = 0;   stride = 512; break;
        case 1:  src = Wz2; dst = g_Wz;  koff = 256; stride = 512; break;
        case 2:  src = Wr1; dst = g_Wr;  koff = 0;   stride = 512; break;
        case 3:  src = Wr2; dst = g_Wr;  koff = 256; stride = 512; break;
        case 4:  src = Wh1; dst = g_Wh1; koff = 0;   stride = 256; break;
        default: src = Wh2; dst = g_Wh2; koff = 0;   stride = 256; break;
    }
    __shared__ float s[32][33];
    int tx = threadIdx.x & 31, ty = threadIdx.x >> 5;
    int n0 = blockIdx.x * 32, k0 = blockIdx.y * 32;
#pragma unroll
    for (int r = 0; r < 4; r++)
        s[ty + 8 * r][tx] = src[(size_t)(k0 + ty + 8 * r) * 256 + n0 + tx];
    __syncthreads();
#pragma unroll
    for (int r = 0; r < 4; r++)
        dst[(size_t)(n0 + ty + 8 * r) * stride + koff + k0 + tx] =
            __float2half_rn(s[tx][ty + 8 * r]);
}

// ---------------------------------------------------------------------------
// MMA on one buffered chunk: 128(M) x 128(N) x 64(K), split-A 2-term.
// ---------------------------------------------------------------------------
__device__ __forceinline__ void mma_chunk_128x128(float acc[4][4][4], u32 sbuf,
                                                  u32 aoff, u32 boff) {
#pragma unroll
    for (int k16 = 0; k16 < 4; k16++) {
        u32 bf[2][4];
        ldsm4(bf[0], sbuf + OFF_B + boff + k16 * 32);
        ldsm4(bf[1], sbuf + OFF_B + boff + 16 * STRB + k16 * 32);
#pragma unroll
        for (int mi = 0; mi < 4; mi++) {
            u32 ah[4], al[4];
            ldsm4(ah, sbuf + OFF_AHI + aoff + mi * 16 * STRB + k16 * 32);
            ldsm4(al, sbuf + OFF_ALO + aoff + mi * 16 * STRB + k16 * 32);
#pragma unroll
            for (int ni = 0; ni < 4; ni++) {
                const u32* bp = &bf[ni >> 1][(ni & 1) * 2];
                mma16816(acc[mi][ni], ah, bp);
                mma16816(acc[mi][ni], al, bp);
            }
        }
    }
}

// ---------------------------------------------------------------------------
// k1: D[128 tok, 128 feat] = A_b @ (X|H)_b slice, -> C hi/lo fp16
// ---------------------------------------------------------------------------
__global__ __launch_bounds__(256, 2) void k1() {
    extern __shared__ char sm[];
    const int tid = threadIdx.x, lane = tid & 31, wid = tid >> 5;
    const int wm = wid >> 2, wn = wid & 3;
    const int hsel = blockIdx.x >> 1, nb = blockIdx.x & 1, b = blockIdx.y;

    const __half* Ah = g_A_hi + (size_t)b * 16384;
    const __half* Al = g_A_lo + (size_t)b * 16384;
    const __half* Bp = (hsel ? g_Ht : g_Xt) + (size_t)b * 32768 + (size_t)nb * 128 * 128;

    u32 sb = smem_u32(sm);
    u32 aoff = (u32)((wm * 64 + (lane & 15)) * STRB + (lane >> 4) * 16);
    u32 boff = (u32)((wn * 32 + (lane & 7) + ((lane >> 4) << 3)) * STRB + ((lane >> 3) & 1) * 16);

    float acc[4][4][4];
#pragma unroll
    for (int a = 0; a < 4; a++)
#pragma unroll
        for (int c = 0; c < 4; c++)
#pragma unroll
            for (int d = 0; d < 4; d++) acc[a][c][d] = 0.0f;

    // prologue: chunk 0 -> buf 0
    cp_tile(sb + OFF_AHI, Ah, 128, 128, tid);
    cp_tile(sb + OFF_ALO, Al, 128, 128, tid);
    cp_tile(sb + OFF_B,   Bp, 128, 128, tid);
    cp_commit();
    // chunk 1 -> buf 1
    cp_tile(sb + BUF_SZ + OFF_AHI, Ah + 64, 128, 128, tid);
    cp_tile(sb + BUF_SZ + OFF_ALO, Al + 64, 128, 128, tid);
    cp_tile(sb + BUF_SZ + OFF_B,   Bp + 64, 128, 128, tid);
    cp_commit();

    cp_wait<1>();
    __syncthreads();
    mma_chunk_128x128(acc, sb, aoff, boff);
    cp_wait<0>();
    __syncthreads();
    mma_chunk_128x128(acc, sb + BUF_SZ, aoff, boff);

    const size_t rowbase = (size_t)b * 128;
    const int colb = hsel * 256 + nb * 128 + wn * 32;
#pragma unroll
    for (int mi = 0; mi < 4; mi++) {
#pragma unroll
        for (int ni = 0; ni < 4; ni++) {
            int r0 = wm * 64 + mi * 16 + (lane >> 2);
            int c  = colb + ni * 8 + (lane & 3) * 2;
#pragma unroll
            for (int half_ = 0; half_ < 2; half_++) {
                size_t row = rowbase + r0 + half_ * 8;
                float x0 = acc[mi][ni][half_ * 2], x1 = acc[mi][ni][half_ * 2 + 1];
                __half h0, l0, h1, l1;
                split2(x0, h0, l0); split2(x1, h1, l1);
                *(__half2*)(g_C_hi + row * 512 + c) = __halves2half2(h0, h1);
                *(__half2*)(g_C_lo + row * 512 + c) = __halves2half2(l0, l1);
            }
        }
    }
}

// ---------------------------------------------------------------------------
// k2: Z/R = sigmoid(C @ W^T + bias), K=512, double-buffered pipeline.
// ---------------------------------------------------------------------------
__global__ __launch_bounds__(256, 2) void k2(const float* __restrict__ bias_z,
                                             const float* __restrict__ bias_r) {
    extern __shared__ char sm[];
    const int tid = threadIdx.x, lane = tid & 31, wid = tid >> 5;
    const int wm = wid >> 2, wn = wid & 3;
    const int gate = blockIdx.x >> 1, nb = blockIdx.x & 1, rt = blockIdx.y;

    const __half* Ah = g_C_hi + (size_t)rt * 128 * 512;
    const __half* Al = g_C_lo + (size_t)rt * 128 * 512;
    const __half* Bp = (gate ? g_Wr : g_Wz) + (size_t)nb * 128 * 512;

    u32 sb = smem_u32(sm);
    u32 aoff = (u32)((wm * 64 + (lane & 15)) * STRB + (lane >> 4) * 16);
    u32 boff = (u32)((wn * 32 + (lane & 7) + ((lane >> 4) << 3)) * STRB + ((lane >> 3) & 1) * 16);

    float acc[4][4][4];
#pragma unroll
    for (int a = 0; a < 4; a++)
#pragma unroll
        for (int c = 0; c < 4; c++)
#pragma unroll
            for (int d = 0; d < 4; d++) acc[a][c][d] = 0.0f;

    // prologue
    cp_tile(sb + OFF_AHI, Ah, 128, 512, tid);
    cp_tile(sb + OFF_ALO, Al, 128, 512, tid);
    cp_tile(sb + OFF_B,   Bp, 128, 512, tid);
    cp_commit();

    for (int ch = 0; ch < 8; ch++) {
        u32 cur = sb + (ch & 1) * BUF_SZ;
        if (ch < 7) {
            u32 nxt = sb + ((ch + 1) & 1) * BUF_SZ;
            cp_tile(nxt + OFF_AHI, Ah + (ch + 1) * 64, 128, 512, tid);
            cp_tile(nxt + OFF_ALO, Al + (ch + 1) * 64, 128, 512, tid);
            cp_tile(nxt + OFF_B,   Bp + (ch + 1) * 64, 128, 512, tid);
            cp_commit();
            cp_wait<1>();
        } else {
            cp_wait<0>();
        }
        __syncthreads();
        mma_chunk_128x128(acc, cur, aoff, boff);
        __syncthreads();   // protect cur before it is refilled as "nxt" next iter
    }

    float* out = gate ? g_R : g_Z;
    const float* bias = gate ? bias_r : bias_z;
#pragma unroll
    for (int mi = 0; mi < 4; mi++) {
#pragma unroll
        for (int ni = 0; ni < 4; ni++) {
            int lr0 = wm * 64 + mi * 16 + (lane >> 2);
            int c   = nb * 128 + wn * 32 + ni * 8 + (lane & 3) * 2;
#pragma unroll
            for (int half_ = 0; half_ < 2; half_++) {
                int lr = lr0 + half_ * 8;
                float2 bb = *(const float2*)(bias + (size_t)lr * 256 + c);
                float2 o;
                o.x = sigmoidf_fast(acc[mi][ni][half_ * 2]     + bb.x);
                o.y = sigmoidf_fast(acc[mi][ni][half_ * 2 + 1] + bb.y);
                *(float2*)(out + ((size_t)rt * 128 + lr) * 256 + c) = o;
            }
        }
    }
}

// ---------------------------------------------------------------------------
// k3: P1 = AX@Wh1, P2 = AH@Wh2 (K=256 each), fused GRU epilogue, pipelined.
// ---------------------------------------------------------------------------
__global__ __launch_bounds__(256, 2) void k3(const float* __restrict__ bias_h,
                                             const float* __restrict__ hidden,
                                             float* __restrict__ Out) {
    extern __shared__ char sm[];
    const int tid = threadIdx.x, lane = tid & 31, wid = tid >> 5;
    const int wm = wid >> 2, wn = wid & 3;
    const int cb = blockIdx.x, rt = blockIdx.y;

    const __half* Ah = g_C_hi + (size_t)rt * 128 * 512;
    const __half* Al = g_C_lo + (size_t)rt * 128 * 512;

    u32 sb = smem_u32(sm);
    u32 aoff = (u32)((wm * 64 + (lane & 15)) * STRB + (lane >> 4) * 16);
    u32 boff = (u32)((wn * 16 + (lane & 7) + ((lane >> 4) << 3)) * STRB + ((lane >> 3) & 1) * 16);

    float acc[2][4][2][4];
#pragma unroll
    for (int p = 0; p < 2; p++)
#pragma unroll
        for (int a = 0; a < 4; a++)
#pragma unroll
            for (int c = 0; c < 2; c++)
#pragma unroll
                for (int d = 0; d < 4; d++) acc[p][a][c][d] = 0.0f;

    // j = P*4 + ch, 8 steps
    {
        const __half* B0 = g_Wh1 + (size_t)cb * 64 * 256;
        cp_tile(sb + OFF_AHI, Ah, 128, 512, tid);
        cp_tile(sb + OFF_ALO, Al, 128, 512, tid);
        cp_tile(sb + OFF_B,   B0, 64, 256, tid);
        cp_commit();
    }
    for (int j = 0; j < 8; j++) {
        u32 cur = sb + (j & 1) * BUF_SZ;
        if (j < 7) {
            int jn = j + 1;
            int Pn = jn >> 2, chn = jn & 3;
            const __half* Bn = (Pn ? g_Wh2 : g_Wh1) + (size_t)cb * 64 * 256;
            u32 nxt = sb + (jn & 1) * BUF_SZ;
            cp_tile(nxt + OFF_AHI, Ah + Pn * 256 + chn * 64, 128, 512, tid);
            cp_tile(nxt + OFF_ALO, Al + Pn * 256 + chn * 64, 128, 512, tid);
            cp_tile(nxt + OFF_B,   Bn + chn * 64, 64, 256, tid);
            cp_commit();
            cp_wait<1>();
        } else {
            cp_wait<0>();
        }
        __syncthreads();
        int P = j >> 2;
#pragma unroll
        for (int k16 = 0; k16 < 4; k16++) {
            u32 bf[4];
            ldsm4(bf, cur + OFF_B + boff + k16 * 32);
#pragma unroll
            for (int mi = 0; mi < 4; mi++) {
                u32 ah[4], al[4];
                ldsm4(ah, cur + OFF_AHI + aoff + mi * 16 * STRB + k16 * 32);
                ldsm4(al, cur + OFF_ALO + aoff + mi * 16 * STRB + k16 * 32);
#pragma unroll
                for (int ni = 0; ni < 2; ni++) {
                    mma16816(acc[P][mi][ni], ah, &bf[ni * 2]);
                    mma16816(acc[P][mi][ni], al, &bf[ni * 2]);
                }
            }
        }
        __syncthreads();
    }

#pragma unroll
    for (int mi = 0; mi < 4; mi++) {
#pragma unroll
        for (int ni = 0; ni < 2; ni++) {
            int lr0 = wm * 64 + mi * 16 + (lane >> 2);
            int c   = cb * 64 + wn * 16 + ni * 8 + (lane & 3) * 2;
#pragma unroll
            for (int half_ = 0; half_ < 2; half_++) {
                int lr = lr0 + half_ * 8;
                size_t off = ((size_t)rt * 128 + lr) * 256 + c;
                float2 zv = *(const float2*)(g_Z + off);
                float2 rv = *(const float2*)(g_R + off);
                float2 hv = *(const float2*)(hidden + off);
                float2 bv = *(const float2*)(bias_h + (size_t)lr * 256 + c);
                float p1x = acc[0][mi][ni][half_ * 2],     p2x = acc[1][mi][ni][half_ * 2];
                float p1y = acc[0][mi][ni][half_ * 2 + 1], p2y = acc[1][mi][ni][half_ * 2 + 1];
                float2 o;
                o.x = zv.x * hv.x + (1.0f - zv.x) * tanhf(p1x + rv.x * p2x + bv.x);
                o.y = zv.y * hv.y + (1.0f - zv.y) * tanhf(p1y + rv.y * p2y + bv.y);
                *(float2*)(Out + off) = o;
            }
        }
    }
}

// ---------------------------------------------------------------------------
extern "C" void kernel_launch(void* const* d_in, const int* in_sizes, int n_in,
                              void* d_out, int out_size) {
    (void)in_sizes; (void)n_in; (void)out_size;
    const float* X      = (const float*)d_in[0];
    const float* A      = (const float*)d_in[1];
    const float* hidden = (const float*)d_in[2];
    const float* Wz1    = (const float*)d_in[3];
    const float* Wz2    = (const float*)d_in[4];
    const float* Wr1    = (const float*)d_in[5];
    const float* Wr2    = (const float*)d_in[6];
    const float* Wh1    = (const float*)d_in[7];
    const float* Wh2    = (const float*)d_in[8];
    const float* bz     = (const float*)d_in[9];
    const float* br     = (const float*)d_in[10];
    const float* bh     = (const float*)d_in[11];
    float* out          = (float*)d_out;

    static bool attr_done = false;
    if (!attr_done) {
        cudaFuncSetAttribute(k1, cudaFuncAttributeMaxDynamicSharedMemorySize, SMEM_TOTAL);
        cudaFuncSetAttribute(k2, cudaFuncAttributeMaxDynamicSharedMemorySize, SMEM_TOTAL);
        cudaFuncSetAttribute(k3, cudaFuncAttributeMaxDynamicSharedMemorySize, SMEM_TOTAL);
        attr_done = true;
    }

    conv_A<<<8192, 256>>>(A);
    conv_XH<<<dim3(8, 4, 1024), 256>>>(X, hidden);
    conv_W<<<dim3(8, 8, 6), 256>>>(Wz1, Wz2, Wr1, Wr2, Wh1, Wh2);

    k1<<<dim3(4, 512), 256, SMEM_TOTAL>>>();
    k2<<<dim3(4, 512), 256, SMEM_TOTAL>>>(bz, br);
    k3<<<dim3(4, 512), 256, SMEM_TOTAL>>>(bh, hidden, out);
}